// round 9
// baseline (speedup 1.0000x reference)
#include <cuda_runtime.h>
#include <cstdint>
#include <cstddef>

#define FULLW 0xffffffffu

// ---------------- static device scratch (allocation is forbidden) ----------------
__device__ float4 g_xyz4[32768];                      // (x,y,z,|p|^2)
__device__ int    g_idx[32768 * 32];                  // 32-NN global point ids
__device__ float  g_h0[(size_t)32768 * 64 * 32];      // z0 [q][64][32]; later z2 ch 0..63
__device__ float  g_h1[(size_t)32768 * 64 * 32];      // z1 [q][64][32]; later z2 ch 64..127
__device__ double g_sum[256];                         // BN sums: L0 0..63, L1 64..127, L2 128..255
__device__ double g_sq[256];
__device__ float  g_scale[256];                       // folded BN affine
__device__ float  g_shift[256];

// ---------------- prep: pack xyz + squared norm, zero stats ----------------
__global__ void prep_k(const float* __restrict__ xyz)
{
    int i = blockIdx.x * 256 + threadIdx.x;           // 0..32767
    float x = xyz[3 * i + 0], y = xyz[3 * i + 1], z = xyz[3 * i + 2];
    g_xyz4[i] = make_float4(x, y, z, x * x + y * y + z * z);
    if (blockIdx.x == 0) {                            // replay-safe stats reset
        g_sum[threadIdx.x] = 0.0;
        g_sq[threadIdx.x]  = 0.0;
    }
}

// monotone float->uint transform (handles tiny negative self-distances)
__device__ __forceinline__ unsigned ford(float f)
{
    unsigned b = __float_as_uint(f);
    return (b & 0x80000000u) ? ~b : (b | 0x80000000u);
}

// ---------------- kNN: warp per query, evict-max top-32 via REDUX ----------------
// Kept key per lane = (ordered_dist & ~31) | lane  -> warp max key identifies both the
// threshold and the lane to evict in a single __reduce_max_sync.
__global__ void knn_k()
{
    int lane  = threadIdx.x & 31;
    int q     = blockIdx.x * 8 + (threadIdx.x >> 5); // 4096 blocks * 8 warps = 32768
    int bbase = q & ~4095;                            // batch start (global point ids)

    float4 cq = g_xyz4[q];
    float  qsq = cq.w;

    unsigned key = 0xFFFFFFE0u | (unsigned)lane;      // "empty" = above any real distance
    unsigned thr = 0xFFFFFFFFu;                       // current max kept key
    int      ki  = bbase;

    for (int base = 0; base < 4096; base += 32) {
        float4 cn  = g_xyz4[bbase + base + lane];
        float  dot = fmaf(cq.x, cn.x, fmaf(cq.y, cn.y, cq.z * cn.z));
        float  d   = fmaf(-2.0f, dot, qsq + cn.w);    // sq_q + sq_c - 2*dot (ref formula)
        unsigned uc = ford(d);

        unsigned m = __ballot_sync(FULLW, uc < (thr & ~31u));
        while (m) {                                   // m is warp-uniform
            int src = __ffs(m) - 1; m &= m - 1;
            unsigned ucs = __shfl_sync(FULLW, uc, src);
            if (ucs < (thr & ~31u)) {                 // warp-uniform recheck vs updated thr
                if (lane == (int)(thr & 31u)) {       // evict current max holder
                    key = (ucs & ~31u) | (unsigned)lane;
                    ki  = bbase + base + src;
                }
                thr = __reduce_max_sync(FULLW, key);  // new threshold (one REDUX)
            }
        }
    }
    g_idx[q * 32 + lane] = ki;                        // coalesced; order within K irrelevant
}

// ---------------- MLP layer: warp per query, lane = neighbor k ----------------
// L=0: gather (xyz diff ++ points) -> z0 -> g_h0
// L=1: relu(BN(z0)) -> z1 -> g_h1
// L=2: relu(BN(z1)) -> z2 -> ch<64 g_h0 (free), ch>=64 g_h1 (own q read before write)
template <int L>
__global__ void __launch_bounds__(256) layer_k(const float* __restrict__ W,
                                               const float* __restrict__ bias,
                                               const float* __restrict__ points)
{
    constexpr int CIN  = (L == 0) ? 67 : 64;
    constexpr int CINP = (L == 0) ? 68 : 64;          // pad to multiple of 4
    constexpr int COUT = (L == 2) ? 128 : 64;
    constexpr int CB   = (L == 2) ? 64 : 0;           // BN channel base of the INPUT

    __shared__ float sw[COUT * CINP];
    __shared__ float sb[COUT];

    int tid = threadIdx.x;
    for (int i = tid; i < COUT * CIN; i += 256) {
        int o = i / CIN, c = i - o * CIN;
        sw[o * CINP + c] = W[i];
    }
    if (CINP > CIN)
        for (int o = tid; o < COUT; o += 256) sw[o * CINP + CIN] = 0.0f;
    if (tid < COUT) sb[tid] = bias[tid];
    __syncthreads();

    int lane = tid & 31;
    int q    = blockIdx.x * 8 + (tid >> 5);

    float f[CINP];
    if (L == 0) {
        int nb = g_idx[q * 32 + lane];
        float4 cq = g_xyz4[q];
        float4 cn = g_xyz4[nb];
        f[0] = cn.x - cq.x; f[1] = cn.y - cq.y; f[2] = cn.z - cq.z;
        const float4* pf = (const float4*)(points + (size_t)nb * 64);
#pragma unroll
        for (int i = 0; i < 16; i++) {
            float4 v = pf[i];
            f[3 + 4 * i] = v.x; f[4 + 4 * i] = v.y;
            f[5 + 4 * i] = v.z; f[6 + 4 * i] = v.w;
        }
        f[67] = 0.0f;
    } else {
        const float* hin = (L == 1) ? g_h0 : g_h1;
        const float* hp  = hin + (size_t)q * 2048 + lane;
#pragma unroll
        for (int c = 0; c < 64; c++) {
            float z = hp[(size_t)c * 32];             // coalesced across lanes
            f[c] = fmaxf(fmaf(z, g_scale[CB + c], g_shift[CB + c]), 0.0f);
        }
    }

    for (int o = 0; o < COUT; o++) {
        float acc = sb[o];
        const float4* wr = (const float4*)(sw + o * CINP);  // broadcast LDS.128
#pragma unroll
        for (int c4 = 0; c4 < CINP / 4; c4++) {
            float4 w = wr[c4];
            acc = fmaf(w.x, f[4 * c4 + 0], acc);
            acc = fmaf(w.y, f[4 * c4 + 1], acc);
            acc = fmaf(w.z, f[4 * c4 + 2], acc);
            acc = fmaf(w.w, f[4 * c4 + 3], acc);
        }
        if (L == 2) {
            if (o < 64) g_h0[(size_t)q * 2048 + o * 32 + lane] = acc;
            else        g_h1[(size_t)q * 2048 + (o - 64) * 32 + lane] = acc;
        } else if (L == 0) {
            g_h0[(size_t)q * 2048 + o * 32 + lane] = acc;
        } else {
            g_h1[(size_t)q * 2048 + o * 32 + lane] = acc;
        }
    }
}

// ---------------- BN stats: column-striding sums over [32768][64][32] ----------------
__global__ void stats_k(int buf, int chan_base)
{
    const float* z = buf ? g_h1 : g_h0;
    int col = blockIdx.x * 256 + threadIdx.x;          // 0..2047 (= ch*32 + k)
    const float* p = z + (size_t)blockIdx.y * 1024 * 2048 + col;
    float s = 0.0f, s2 = 0.0f;
#pragma unroll 8
    for (int i = 0; i < 1024; i++) {                   // 128B coalesced per warp-iter
        float v = p[(size_t)i * 2048];
        s += v;
        s2 = fmaf(v, v, s2);
    }
    int ch = chan_base + (col >> 5);
    atomicAdd(&g_sum[ch], (double)s);
    atomicAdd(&g_sq[ch],  (double)s2);
}

// ---------------- fold BN (batch stats) into scale/shift ----------------
__global__ void finalize_k(const float* __restrict__ g, const float* __restrict__ beta,
                           int chan_base, int n)
{
    int o = threadIdx.x;
    if (o >= n) return;
    const double cnt = 1048576.0;                      // 8*4096*32
    double mean = g_sum[chan_base + o] / cnt;
    double var  = g_sq[chan_base + o] / cnt - mean * mean;   // biased, matches ref
    if (var < 0.0) var = 0.0;
    double sc = (double)g[o] / sqrt(var + 1e-5);
    g_scale[chan_base + o] = (float)sc;
    g_shift[chan_base + o] = (float)((double)beta[o] - mean * sc);
}

// ---------------- epilogue: max over K folded through monotone BN+ReLU ----------------
__global__ void out_k(float* __restrict__ out)
{
    int idx = blockIdx.x * 256 + threadIdx.x;          // q*128 + o
    int q = idx >> 7, o = idx & 127;
    const float* zp = ((o < 64) ? g_h0 : g_h1) + (size_t)q * 2048 + (o & 63) * 32;
    const float4* z4 = (const float4*)zp;
    float mx = -3.402823466e38f, mn = 3.402823466e38f;
#pragma unroll
    for (int i = 0; i < 8; i++) {
        float4 v = z4[i];
        mx = fmaxf(mx, fmaxf(fmaxf(v.x, v.y), fmaxf(v.z, v.w)));
        mn = fminf(mn, fminf(fminf(v.x, v.y), fminf(v.z, v.w)));
    }
    float a = g_scale[128 + o], c = g_shift[128 + o];
    float m = (a >= 0.0f) ? mx : mn;                   // max_k relu(a z + c)
    out[idx] = fmaxf(fmaf(a, m, c), 0.0f);
}

// ---------------- launch: linear chain, graph-capturable ----------------
extern "C" void kernel_launch(void* const* d_in, const int* in_sizes, int n_in,
                              void* d_out, int out_size)
{
    const float* xyz    = (const float*)d_in[0];
    const float* points = (const float*)d_in[1];
    const float* W0  = (const float*)d_in[2];
    const float* b0  = (const float*)d_in[3];
    const float* g0  = (const float*)d_in[4];
    const float* be0 = (const float*)d_in[5];
    const float* W1  = (const float*)d_in[6];
    const float* b1  = (const float*)d_in[7];
    const float* g1  = (const float*)d_in[8];
    const float* be1 = (const float*)d_in[9];
    const float* W2  = (const float*)d_in[10];
    const float* b2  = (const float*)d_in[11];
    const float* g2  = (const float*)d_in[12];
    const float* be2 = (const float*)d_in[13];
    float* out = (float*)d_out;
    (void)in_sizes; (void)n_in; (void)out_size;       // nsample fixed at 32

    prep_k<<<128, 256>>>(xyz);
    knn_k<<<4096, 256>>>();

    layer_k<0><<<4096, 256>>>(W0, b0, points);
    stats_k<<<dim3(8, 32), 256>>>(0, 0);
    finalize_k<<<1, 128>>>(g0, be0, 0, 64);

    layer_k<1><<<4096, 256>>>(W1, b1, nullptr);
    stats_k<<<dim3(8, 32), 256>>>(1, 64);
    finalize_k<<<1, 128>>>(g1, be1, 64, 64);

    layer_k<2><<<4096, 256>>>(W2, b2, nullptr);
    stats_k<<<dim3(8, 32), 256>>>(0, 128);
    stats_k<<<dim3(8, 32), 256>>>(1, 192);
    finalize_k<<<1, 128>>>(g2, be2, 128, 128);

    out_k<<<16384, 256>>>(out);
}

// round 10
// speedup vs baseline: 1.0020x; 1.0020x over previous
#include <cuda_runtime.h>
#include <cstdint>
#include <cstddef>

#define FULLW 0xffffffffu

// ---------------- static device scratch (allocation is forbidden) ----------------
__device__ float4 g_xyz4[32768];                      // (x,y,z,|p|^2)
__device__ int    g_idx[32768 * 32];                  // 32-NN global point ids
__device__ float  g_h0[(size_t)32768 * 64 * 32];      // z0 [q][64][32]; later z2 ch 0..63
__device__ float  g_h1[(size_t)32768 * 64 * 32];      // z1 [q][64][32]; later z2 ch 64..127
__device__ float2 g_mm[(size_t)32768 * 128];          // per (q,ch): (max_k z2, min_k z2)
__device__ double g_sum[256];                         // BN sums: L0 0..63, L1 64..127, L2 128..255
__device__ double g_sq[256];
__device__ float  g_scale[256];                       // folded BN affine
__device__ float  g_shift[256];

// ---------------- packed f32x2 helpers (exact fp32 semantics) ----------------
__device__ __forceinline__ unsigned long long pack2(float lo, float hi)
{
    unsigned long long r;
    asm("mov.b64 %0, {%1,%2};" : "=l"(r) : "f"(lo), "f"(hi));
    return r;
}
__device__ __forceinline__ void unpack2(unsigned long long v, float& lo, float& hi)
{
    asm("mov.b64 {%0,%1}, %2;" : "=f"(lo), "=f"(hi) : "l"(v));
}
__device__ __forceinline__ unsigned long long ffma2(unsigned long long a,
                                                    unsigned long long b,
                                                    unsigned long long c)
{
    unsigned long long d;
    asm("fma.rn.f32x2 %0, %1, %2, %3;" : "=l"(d) : "l"(a), "l"(b), "l"(c));
    return d;
}

// monotone float<->uint order transform
__device__ __forceinline__ unsigned ford(float f)
{
    unsigned b = __float_as_uint(f);
    return (b & 0x80000000u) ? ~b : (b | 0x80000000u);
}
__device__ __forceinline__ float iford(unsigned u)
{
    unsigned b = (u & 0x80000000u) ? (u & 0x7fffffffu) : ~u;
    return __uint_as_float(b);
}

// ---------------- prep: pack xyz + squared norm, zero stats ----------------
__global__ void prep_k(const float* __restrict__ xyz)
{
    int i = blockIdx.x * 256 + threadIdx.x;           // 0..32767
    float x = xyz[3 * i + 0], y = xyz[3 * i + 1], z = xyz[3 * i + 2];
    g_xyz4[i] = make_float4(x, y, z, x * x + y * y + z * z);
    if (blockIdx.x == 0) {                            // replay-safe stats reset
        g_sum[threadIdx.x] = 0.0;
        g_sq[threadIdx.x]  = 0.0;
    }
}

// ---------------- kNN: warp per query, evict-max top-32 via REDUX ----------------
__global__ void knn_k()
{
    int lane  = threadIdx.x & 31;
    int q     = blockIdx.x * 8 + (threadIdx.x >> 5);  // 4096 blocks * 8 warps
    int bbase = q & ~4095;                            // batch start (global point ids)

    float4 cq = g_xyz4[q];
    float  qsq = cq.w;

    unsigned key = 0xFFFFFFE0u | (unsigned)lane;      // "empty" sentinel
    unsigned thr = 0xFFFFFFFFu;                       // current max kept key
    int      ki  = bbase;

    for (int base = 0; base < 4096; base += 32) {
        float4 cn  = g_xyz4[bbase + base + lane];
        float  dot = fmaf(cq.x, cn.x, fmaf(cq.y, cn.y, cq.z * cn.z));
        float  d   = fmaf(-2.0f, dot, qsq + cn.w);    // ref formula
        unsigned uc = ford(d);

        unsigned m = __ballot_sync(FULLW, uc < (thr & ~31u));
        while (m) {                                   // warp-uniform
            int src = __ffs(m) - 1; m &= m - 1;
            unsigned ucs = __shfl_sync(FULLW, uc, src);
            if (ucs < (thr & ~31u)) {
                if (lane == (int)(thr & 31u)) {       // evict current max holder
                    key = (ucs & ~31u) | (unsigned)lane;
                    ki  = bbase + base + src;
                }
                thr = __reduce_max_sync(FULLW, key);
            }
        }
    }
    g_idx[q * 32 + lane] = ki;
}

// ---------------- MLP layer: warp per query, lane = neighbor k, f32x2 math ----------------
// Weights staged TRANSPOSED in smem: swt[c][o], so output-channel pairs are contiguous.
template <int L>
__global__ void __launch_bounds__(256) layer_k(const float* __restrict__ W,
                                               const float* __restrict__ bias,
                                               const float* __restrict__ points)
{
    constexpr int CIN  = (L == 0) ? 67 : 64;
    constexpr int CINP = (L == 0) ? 68 : 64;
    constexpr int COUT = (L == 2) ? 128 : 64;
    constexpr int CB   = (L == 2) ? 64 : 0;           // BN base of the INPUT
    constexpr int NH   = COUT / 64;                   // output halves

    __shared__ float swt[CINP * COUT];                // [c][o]
    __shared__ float sb[COUT];

    int tid = threadIdx.x;
    for (int i = tid; i < COUT * CIN; i += 256) {
        int o = i / CIN, c = i - o * CIN;
        swt[c * COUT + o] = W[i];                     // transpose on the fly
    }
    if (CINP > CIN)
        for (int o = tid; o < COUT; o += 256) swt[CIN * COUT + o] = 0.0f;
    if (tid < COUT) sb[tid] = bias[tid];
    __syncthreads();

    int lane = tid & 31;
    int q    = blockIdx.x * 8 + (tid >> 5);

    float f[CINP];
    if (L == 0) {
        int nb = g_idx[q * 32 + lane];
        float4 cq = g_xyz4[q];
        float4 cn = g_xyz4[nb];
        f[0] = cn.x - cq.x; f[1] = cn.y - cq.y; f[2] = cn.z - cq.z;
        const float4* pf = (const float4*)(points + (size_t)nb * 64);
#pragma unroll
        for (int i = 0; i < 16; i++) {
            float4 v = pf[i];
            f[3 + 4 * i] = v.x; f[4 + 4 * i] = v.y;
            f[5 + 4 * i] = v.z; f[6 + 4 * i] = v.w;
        }
        f[67] = 0.0f;
    } else {
        const float* hin = (L == 1) ? g_h0 : g_h1;
        const float* hp  = hin + (size_t)q * 2048 + lane;
#pragma unroll
        for (int c = 0; c < 64; c++) {
            float z = hp[(size_t)c * 32];             // coalesced across lanes
            f[c] = fmaxf(fmaf(z, g_scale[CB + c], g_shift[CB + c]), 0.0f);
        }
    }

#pragma unroll
    for (int h = 0; h < NH; h++) {
        unsigned long long acc[32];
#pragma unroll
        for (int p = 0; p < 32; p++)
            acc[p] = pack2(sb[h * 64 + 2 * p], sb[h * 64 + 2 * p + 1]);

#pragma unroll 4
        for (int c = 0; c < CINP; c++) {
            unsigned long long f2 = pack2(f[c], f[c]);
            const ulonglong2* wr = (const ulonglong2*)(swt + c * COUT + h * 64);
#pragma unroll
            for (int p2 = 0; p2 < 16; p2++) {         // broadcast LDS.128 -> 2 pairs
                ulonglong2 w = wr[p2];
                acc[2 * p2 + 0] = ffma2(w.x, f2, acc[2 * p2 + 0]);
                acc[2 * p2 + 1] = ffma2(w.y, f2, acc[2 * p2 + 1]);
            }
        }

        float* dst;
        if (L == 0)      dst = g_h0 + (size_t)q * 2048 + lane;
        else if (L == 1) dst = g_h1 + (size_t)q * 2048 + lane;
        else             dst = ((h == 0) ? g_h0 : g_h1) + (size_t)q * 2048 + lane;
#pragma unroll
        for (int p = 0; p < 32; p++) {
            float lo, hi;
            unpack2(acc[p], lo, hi);
            dst[(size_t)(2 * p + 0) * 32] = lo;
            dst[(size_t)(2 * p + 1) * 32] = hi;
        }
    }
}

// ---------------- BN stats (layers 0/1): column-strided, warp-reduced atomics ----------------
__global__ void stats_k(int buf, int chan_base)
{
    const float* z = buf ? g_h1 : g_h0;
    int col   = blockIdx.x * 256 + threadIdx.x;        // 0..2047 (= ch*32 + k)
    int qbase = blockIdx.y * 256;
    const float* p = z + (size_t)qbase * 2048 + col;
    float s = 0.0f, s2 = 0.0f;
#pragma unroll 8
    for (int i = 0; i < 256; i++) {
        float v = p[(size_t)i * 2048];
        s += v;
        s2 = fmaf(v, v, s2);
    }
#pragma unroll
    for (int off = 16; off; off >>= 1) {               // warp spans exactly one channel
        s  += __shfl_xor_sync(FULLW, s,  off);
        s2 += __shfl_xor_sync(FULLW, s2, off);
    }
    if ((threadIdx.x & 31) == 0) {
        int ch = chan_base + (col >> 5);
        atomicAdd(&g_sum[ch], (double)s);
        atomicAdd(&g_sq[ch],  (double)s2);
    }
}

// ---------------- layer-2 stats FUSED with per-(q,ch) max/min over K ----------------
// Warp lanes = the 32 neighbors of one (q,ch) row, so REDUX gives max/min for free.
__global__ void stats2_k(int buf)
{
    const float* z = buf ? g_h1 : g_h0;
    int ch_off = buf ? 64 : 0;                         // output-channel offset in z2
    int lane   = threadIdx.x & 31;
    int col    = blockIdx.x * 256 + threadIdx.x;       // ch_local*32 + k
    int ch_l   = col >> 5;
    int qbase  = blockIdx.y * 256;
    const float* p = z + (size_t)qbase * 2048 + col;
    float s = 0.0f, s2 = 0.0f;
#pragma unroll 4
    for (int i = 0; i < 256; i++) {
        float v = p[(size_t)i * 2048];
        s += v;
        s2 = fmaf(v, v, s2);
        unsigned fo = ford(v);
        unsigned mx = __reduce_max_sync(FULLW, fo);
        unsigned mn = __reduce_min_sync(FULLW, fo);
        if (lane == 0)
            g_mm[(size_t)(qbase + i) * 128 + ch_off + ch_l] =
                make_float2(iford(mx), iford(mn));
    }
#pragma unroll
    for (int off = 16; off; off >>= 1) {
        s  += __shfl_xor_sync(FULLW, s,  off);
        s2 += __shfl_xor_sync(FULLW, s2, off);
    }
    if (lane == 0) {
        int ch = 128 + ch_off + ch_l;
        atomicAdd(&g_sum[ch], (double)s);
        atomicAdd(&g_sq[ch],  (double)s2);
    }
}

// ---------------- fold BN (batch stats) into scale/shift ----------------
__global__ void finalize_k(const float* __restrict__ g, const float* __restrict__ beta,
                           int chan_base, int n)
{
    int o = threadIdx.x;
    if (o >= n) return;
    const double cnt = 1048576.0;                      // 8*4096*32
    double mean = g_sum[chan_base + o] / cnt;
    double var  = g_sq[chan_base + o] / cnt - mean * mean;   // biased, matches ref
    if (var < 0.0) var = 0.0;
    double sc = (double)g[o] / sqrt(var + 1e-5);
    g_scale[chan_base + o] = (float)sc;
    g_shift[chan_base + o] = (float)((double)beta[o] - mean * sc);
}

// ---------------- tiny epilogue: monotone BN+ReLU through stored max/min ----------------
__global__ void out_k(float* __restrict__ out)
{
    int idx = blockIdx.x * 256 + threadIdx.x;          // q*128 + o
    int o = idx & 127;
    float2 mm = g_mm[idx];
    float a = g_scale[128 + o], c = g_shift[128 + o];
    float m = (a >= 0.0f) ? mm.x : mm.y;               // max_k relu(a z + c)
    out[idx] = fmaxf(fmaf(a, m, c), 0.0f);
}

// ---------------- launch: linear chain, graph-capturable ----------------
extern "C" void kernel_launch(void* const* d_in, const int* in_sizes, int n_in,
                              void* d_out, int out_size)
{
    const float* xyz    = (const float*)d_in[0];
    const float* points = (const float*)d_in[1];
    const float* W0  = (const float*)d_in[2];
    const float* b0  = (const float*)d_in[3];
    const float* g0  = (const float*)d_in[4];
    const float* be0 = (const float*)d_in[5];
    const float* W1  = (const float*)d_in[6];
    const float* b1  = (const float*)d_in[7];
    const float* g1  = (const float*)d_in[8];
    const float* be1 = (const float*)d_in[9];
    const float* W2  = (const float*)d_in[10];
    const float* b2  = (const float*)d_in[11];
    const float* g2  = (const float*)d_in[12];
    const float* be2 = (const float*)d_in[13];
    float* out = (float*)d_out;
    (void)in_sizes; (void)n_in; (void)out_size;

    prep_k<<<128, 256>>>(xyz);
    knn_k<<<4096, 256>>>();

    layer_k<0><<<4096, 256>>>(W0, b0, points);
    stats_k<<<dim3(8, 128), 256>>>(0, 0);
    finalize_k<<<1, 128>>>(g0, be0, 0, 64);

    layer_k<1><<<4096, 256>>>(W1, b1, nullptr);
    stats_k<<<dim3(8, 128), 256>>>(1, 64);
    finalize_k<<<1, 128>>>(g1, be1, 64, 64);

    layer_k<2><<<4096, 256>>>(W2, b2, nullptr);
    stats2_k<<<dim3(8, 128), 256>>>(0);
    stats2_k<<<dim3(8, 128), 256>>>(1);
    finalize_k<<<1, 128>>>(g2, be2, 128, 128);

    out_k<<<16384, 256>>>(out);
}

// round 13
// speedup vs baseline: 1.1975x; 1.1951x over previous
#include <cuda_runtime.h>
#include <cstdint>
#include <cstddef>

#define FULLW 0xffffffffu
typedef unsigned long long ull;

// ---------------- static device scratch (allocation is forbidden) ----------------
__device__ float4 g_xyz4[32768];                      // (x,y,z,|p|^2)
__device__ int    g_idx[32768 * 32];                  // 32-NN global point ids
__device__ float  g_P[32768 * 64];                    // per-point partial of z0 (8MB, L2-resident)
__device__ float  g_Q[32768 * 64];                    // per-query partial of z0
__device__ float  g_z1[(size_t)32768 * 64 * 32];      // z1 [q][64][32]
__device__ float2 g_mm[(size_t)32768 * 128];          // per (q,ch): (max_k z2, min_k z2)
__device__ double g_sum[256];                         // BN sums: L0 0..63, L1 64..127, L2 128..255
__device__ double g_sq[256];
__device__ float  g_scale[256];                       // folded BN affine
__device__ float  g_shift[256];

// ---------------- packed f32x2 helpers (exact fp32 semantics) ----------------
__device__ __forceinline__ ull pack2(float lo, float hi)
{
    ull r; asm("mov.b64 %0, {%1,%2};" : "=l"(r) : "f"(lo), "f"(hi)); return r;
}
__device__ __forceinline__ void unpack2(ull v, float& lo, float& hi)
{
    asm("mov.b64 {%0,%1}, %2;" : "=f"(lo), "=f"(hi) : "l"(v));
}
__device__ __forceinline__ ull ffma2(ull a, ull b, ull c)
{
    ull d; asm("fma.rn.f32x2 %0, %1, %2, %3;" : "=l"(d) : "l"(a), "l"(b), "l"(c)); return d;
}
__device__ __forceinline__ ull fmul2(ull a, ull b)
{
    ull d; asm("mul.rn.f32x2 %0, %1, %2;" : "=l"(d) : "l"(a), "l"(b)); return d;
}
__device__ __forceinline__ ull fadd2(ull a, ull b)
{
    ull d; asm("add.rn.f32x2 %0, %1, %2;" : "=l"(d) : "l"(a), "l"(b)); return d;
}

// monotone float<->uint order transform
__device__ __forceinline__ unsigned ford(float f)
{
    unsigned b = __float_as_uint(f);
    return (b & 0x80000000u) ? ~b : (b | 0x80000000u);
}
__device__ __forceinline__ float iford(unsigned u)
{
    unsigned b = (u & 0x80000000u) ? (u & 0x7fffffffu) : ~u;
    return __uint_as_float(b);
}

// ---------------- prep: pack xyz + squared norm, zero stats ----------------
__global__ void prep_k(const float* __restrict__ xyz)
{
    int i = blockIdx.x * 256 + threadIdx.x;           // 0..32767
    float x = xyz[3 * i + 0], y = xyz[3 * i + 1], z = xyz[3 * i + 2];
    g_xyz4[i] = make_float4(x, y, z, x * x + y * y + z * z);
    if (blockIdx.x == 0) {                            // replay-safe stats reset
        g_sum[threadIdx.x] = 0.0;
        g_sq[threadIdx.x]  = 0.0;
    }
}

// ---------------- P/Q tables: z0[q,k,o] = P[nb][o] + Q[q][o] ----------------
// P[p][o] = W0[o,0:3].xyz[p] + W0[o,3:67].points[p];  Q[q][o] = b0[o] - W0[o,0:3].xyz[q]
__global__ void __launch_bounds__(256) pq_k(const float* __restrict__ W0,
                                            const float* __restrict__ b0,
                                            const float* __restrict__ points)
{
    __shared__ float swt[67 * 64];                    // [c][o]
    int tid = threadIdx.x;
    for (int i = tid; i < 64 * 67; i += 256) {
        int o = i / 67, c = i - o * 67;
        swt[c * 64 + o] = W0[i];
    }
    __syncthreads();

    int lane = tid & 31;
    int p    = blockIdx.x * 8 + (tid >> 5);

    float f[67];
    float4 cp = g_xyz4[p];
    f[0] = cp.x; f[1] = cp.y; f[2] = cp.z;
    const float4* pf = (const float4*)(points + (size_t)p * 64);   // broadcast within warp
#pragma unroll
    for (int i = 0; i < 16; i++) {
        float4 v = pf[i];
        f[3 + 4 * i] = v.x; f[4 + 4 * i] = v.y;
        f[5 + 4 * i] = v.z; f[6 + 4 * i] = v.w;
    }

#pragma unroll
    for (int h = 0; h < 2; h++) {
        int o = h * 32 + lane;
        float acc = 0.0f;
#pragma unroll 16
        for (int c = 0; c < 67; c++)
            acc = fmaf(swt[c * 64 + o], f[c], acc);
        g_P[p * 64 + o] = acc;
        float qv = b0[o] - fmaf(swt[o], f[0],
                         fmaf(swt[64 + o], f[1], swt[128 + o] * f[2]));
        g_Q[p * 64 + o] = qv;
    }
}

// ---------------- kNN: warp per query, evict-max top-32 via REDUX ----------------
__global__ void knn_k()
{
    int lane  = threadIdx.x & 31;
    int q     = blockIdx.x * 8 + (threadIdx.x >> 5);
    int bbase = q & ~4095;

    float4 cq = g_xyz4[q];
    float  qsq = cq.w;

    unsigned key = 0xFFFFFFE0u | (unsigned)lane;
    unsigned thr = 0xFFFFFFFFu;
    int      ki  = bbase;

    for (int base = 0; base < 4096; base += 32) {
        float4 cn  = g_xyz4[bbase + base + lane];
        float  dot = fmaf(cq.x, cn.x, fmaf(cq.y, cn.y, cq.z * cn.z));
        float  d   = fmaf(-2.0f, dot, qsq + cn.w);
        unsigned uc = ford(d);

        unsigned m = __ballot_sync(FULLW, uc < (thr & ~31u));
        while (m) {
            int src = __ffs(m) - 1; m &= m - 1;
            unsigned ucs = __shfl_sync(FULLW, uc, src);
            if (ucs < (thr & ~31u)) {
                if (lane == (int)(thr & 31u)) {
                    key = (ucs & ~31u) | (unsigned)lane;
                    ki  = bbase + base + src;
                }
                thr = __reduce_max_sync(FULLW, key);
            }
        }
    }
    g_idx[q * 32 + lane] = ki;
}

// ---------------- stats of z0 (never materialized): gather P+Q, butterfly reduce ----------------
__global__ void __launch_bounds__(256) stats0_k()
{
    __shared__ float ss[64], ss2[64];
    int tid = threadIdx.x;
    if (tid < 64) { ss[tid] = 0.0f; ss2[tid] = 0.0f; }
    __syncthreads();

    int lane = tid & 31;
    int q    = blockIdx.x * 8 + (tid >> 5);
    int nb   = g_idx[q * 32 + lane];
    const float4* pp = (const float4*)(g_P + (size_t)nb * 64);
    const float4* qq = (const float4*)(g_Q + (size_t)q * 64);

    ull my_s = 0, my_s2 = 0;
#pragma unroll
    for (int i = 0; i < 16; i++) {
        float4 a = pp[i], b = qq[i];
        ull z0 = pack2(a.x + b.x, a.y + b.y);
        ull z1 = pack2(a.z + b.z, a.w + b.w);
        ull q0 = fmul2(z0, z0), q1 = fmul2(z1, z1);
#pragma unroll
        for (int off = 16; off; off >>= 1) {
            z0 = fadd2(z0, __shfl_xor_sync(FULLW, z0, off));
            z1 = fadd2(z1, __shfl_xor_sync(FULLW, z1, off));
            q0 = fadd2(q0, __shfl_xor_sync(FULLW, q0, off));
            q1 = fadd2(q1, __shfl_xor_sync(FULLW, q1, off));
        }
        if (lane == 2 * i)     { my_s = z0; my_s2 = q0; }   // owner keeps pair lane
        if (lane == 2 * i + 1) { my_s = z1; my_s2 = q1; }
    }
    float slo, shi, tlo, thi;
    unpack2(my_s, slo, shi); unpack2(my_s2, tlo, thi);
    atomicAdd(&ss[2 * lane], slo);  atomicAdd(&ss[2 * lane + 1], shi);
    atomicAdd(&ss2[2 * lane], tlo); atomicAdd(&ss2[2 * lane + 1], thi);
    __syncthreads();
    if (tid < 64) {
        atomicAdd(&g_sum[tid], (double)ss[tid]);
        atomicAdd(&g_sq[tid],  (double)ss2[tid]);
    }
}

// ---------------- layer 1: gather z0 from P/Q, BN+ReLU, GEMM 64x64 (f32x2) ----------------
__global__ void __launch_bounds__(256) layer1_k(const float* __restrict__ W1,
                                                const float* __restrict__ b1)
{
    __shared__ float swt[64 * 64];                    // [c][o]
    __shared__ float sb[64];
    int tid = threadIdx.x;
    for (int i = tid; i < 64 * 64; i += 256) {
        int o = i >> 6, c = i & 63;
        swt[c * 64 + o] = W1[i];
    }
    if (tid < 64) sb[tid] = b1[tid];
    __syncthreads();

    int lane = tid & 31;
    int q    = blockIdx.x * 8 + (tid >> 5);
    int nb   = g_idx[q * 32 + lane];
    const float4* pp = (const float4*)(g_P + (size_t)nb * 64);
    const float4* qq = (const float4*)(g_Q + (size_t)q * 64);

    float f[64];
#pragma unroll
    for (int i = 0; i < 16; i++) {
        float4 a = pp[i], b = qq[i];
        f[4 * i + 0] = fmaxf(fmaf(a.x + b.x, g_scale[4 * i + 0], g_shift[4 * i + 0]), 0.0f);
        f[4 * i + 1] = fmaxf(fmaf(a.y + b.y, g_scale[4 * i + 1], g_shift[4 * i + 1]), 0.0f);
        f[4 * i + 2] = fmaxf(fmaf(a.z + b.z, g_scale[4 * i + 2], g_shift[4 * i + 2]), 0.0f);
        f[4 * i + 3] = fmaxf(fmaf(a.w + b.w, g_scale[4 * i + 3], g_shift[4 * i + 3]), 0.0f);
    }

    float* dst = g_z1 + (size_t)q * 2048 + lane;
#pragma unroll
    for (int h = 0; h < 2; h++) {                     // 32-output chunks: 16 u64 accs
        ull acc[16];
#pragma unroll
        for (int p = 0; p < 16; p++)
            acc[p] = pack2(sb[h * 32 + 2 * p], sb[h * 32 + 2 * p + 1]);
#pragma unroll 16
        for (int c = 0; c < 64; c++) {
            ull f2 = pack2(f[c], f[c]);
            const ulonglong2* wr = (const ulonglong2*)(swt + c * 64 + h * 32);
#pragma unroll
            for (int p2 = 0; p2 < 8; p2++) {          // FIX: 8 ulonglong2 = 16 pairs = 32 ch
                ulonglong2 w = wr[p2];
                acc[2 * p2 + 0] = ffma2(w.x, f2, acc[2 * p2 + 0]);
                acc[2 * p2 + 1] = ffma2(w.y, f2, acc[2 * p2 + 1]);
            }
        }
#pragma unroll
        for (int p = 0; p < 16; p++) {
            float lo, hi; unpack2(acc[p], lo, hi);
            dst[(size_t)(h * 32 + 2 * p + 0) * 32] = lo;
            dst[(size_t)(h * 32 + 2 * p + 1) * 32] = hi;
        }
    }
}

// ---------------- BN stats over z1 (coalesced column-strided) ----------------
__global__ void stats1_k()
{
    int col   = blockIdx.x * 256 + threadIdx.x;        // 0..2047
    int qbase = blockIdx.y * 256;
    const float* p = g_z1 + (size_t)qbase * 2048 + col;
    float s = 0.0f, s2 = 0.0f;
#pragma unroll 8
    for (int i = 0; i < 256; i++) {
        float v = p[(size_t)i * 2048];
        s += v;
        s2 = fmaf(v, v, s2);
    }
#pragma unroll
    for (int off = 16; off; off >>= 1) {               // warp spans exactly one channel
        s  += __shfl_xor_sync(FULLW, s,  off);
        s2 += __shfl_xor_sync(FULLW, s2, off);
    }
    if ((threadIdx.x & 31) == 0) {
        int ch = 64 + (col >> 5);
        atomicAdd(&g_sum[ch], (double)s);
        atomicAdd(&g_sq[ch],  (double)s2);
    }
}

// ---------------- layer 2: GEMM 64x128 + fused per-(q,ch) max/min + BN stats ----------------
// z2 is never written to HBM.
__global__ void __launch_bounds__(256) layer2_k(const float* __restrict__ W2,
                                                const float* __restrict__ b2)
{
    __shared__ float swt[64 * 128];                   // [c][o]
    __shared__ float sb[128];
    __shared__ float ss[128], ss2[128];
    int tid = threadIdx.x;
    for (int i = tid; i < 128 * 64; i += 256) {
        int o = i >> 6, c = i & 63;
        swt[c * 128 + o] = W2[i];
    }
    if (tid < 128) { sb[tid] = b2[tid]; ss[tid] = 0.0f; ss2[tid] = 0.0f; }
    __syncthreads();

    int lane = tid & 31;
    int q    = blockIdx.x * 8 + (tid >> 5);
    const float* src = g_z1 + (size_t)q * 2048 + lane;

    float f[64];
#pragma unroll
    for (int c = 0; c < 64; c++) {
        float z = src[(size_t)c * 32];                // coalesced
        f[c] = fmaxf(fmaf(z, g_scale[64 + c], g_shift[64 + c]), 0.0f);
    }

#pragma unroll
    for (int h = 0; h < 4; h++) {                     // 4 chunks of 32 outputs
        ull acc[16];
#pragma unroll
        for (int p = 0; p < 16; p++)
            acc[p] = pack2(sb[h * 32 + 2 * p], sb[h * 32 + 2 * p + 1]);
#pragma unroll 16
        for (int c = 0; c < 64; c++) {
            ull f2 = pack2(f[c], f[c]);
            const ulonglong2* wr = (const ulonglong2*)(swt + c * 128 + h * 32);
#pragma unroll
            for (int p2 = 0; p2 < 8; p2++) {          // FIX: full 32-channel chunk
                ulonglong2 w = wr[p2];
                acc[2 * p2 + 0] = ffma2(w.x, f2, acc[2 * p2 + 0]);
                acc[2 * p2 + 1] = ffma2(w.y, f2, acc[2 * p2 + 1]);
            }
        }

        // fused epilogue: REDUX max/min per channel + butterfly sums (no z2 store)
        ull my_s = 0, my_s2 = 0;
        float2 m0 = make_float2(0, 0), m1 = make_float2(0, 0);
#pragma unroll
        for (int p = 0; p < 16; p++) {
            float lo, hi; unpack2(acc[p], lo, hi);
            unsigned mxlo = __reduce_max_sync(FULLW, ford(lo));
            unsigned mnlo = __reduce_min_sync(FULLW, ford(lo));
            unsigned mxhi = __reduce_max_sync(FULLW, ford(hi));
            unsigned mnhi = __reduce_min_sync(FULLW, ford(hi));
            ull s = acc[p], s2 = fmul2(acc[p], acc[p]);
#pragma unroll
            for (int off = 16; off; off >>= 1) {
                s  = fadd2(s,  __shfl_xor_sync(FULLW, s,  off));
                s2 = fadd2(s2, __shfl_xor_sync(FULLW, s2, off));
            }
            if (lane == p) {
                my_s = s; my_s2 = s2;
                m0 = make_float2(iford(mxlo), iford(mnlo));
                m1 = make_float2(iford(mxhi), iford(mnhi));
            }
        }
        if (lane < 16) {
            int ch = h * 32 + 2 * lane;
            g_mm[(size_t)q * 128 + ch]     = m0;
            g_mm[(size_t)q * 128 + ch + 1] = m1;
            float slo, shi, tlo, thi;
            unpack2(my_s, slo, shi); unpack2(my_s2, tlo, thi);
            atomicAdd(&ss[ch], slo);      atomicAdd(&ss[ch + 1], shi);
            atomicAdd(&ss2[ch], tlo);     atomicAdd(&ss2[ch + 1], thi);
        }
    }
    __syncthreads();
    if (tid < 128) {
        atomicAdd(&g_sum[128 + tid], (double)ss[tid]);
        atomicAdd(&g_sq[128 + tid],  (double)ss2[tid]);
    }
}

// ---------------- fold BN (batch stats) into scale/shift ----------------
__global__ void finalize_k(const float* __restrict__ g, const float* __restrict__ beta,
                           int chan_base, int n)
{
    int o = threadIdx.x;
    if (o >= n) return;
    const double cnt = 1048576.0;                      // 8*4096*32
    double mean = g_sum[chan_base + o] / cnt;
    double var  = g_sq[chan_base + o] / cnt - mean * mean;   // biased, matches ref
    if (var < 0.0) var = 0.0;
    double sc = (double)g[o] / sqrt(var + 1e-5);
    g_scale[chan_base + o] = (float)sc;
    g_shift[chan_base + o] = (float)((double)beta[o] - mean * sc);
}

// ---------------- tiny epilogue: monotone BN+ReLU through stored max/min ----------------
__global__ void out_k(float* __restrict__ out)
{
    int idx = blockIdx.x * 256 + threadIdx.x;          // q*128 + o
    int o = idx & 127;
    float2 mm = g_mm[idx];
    float a = g_scale[128 + o], c = g_shift[128 + o];
    float m = (a >= 0.0f) ? mm.x : mm.y;               // max_k relu(a z + c)
    out[idx] = fmaxf(fmaf(a, m, c), 0.0f);
}

// ---------------- launch: linear chain, graph-capturable ----------------
extern "C" void kernel_launch(void* const* d_in, const int* in_sizes, int n_in,
                              void* d_out, int out_size)
{
    const float* xyz    = (const float*)d_in[0];
    const float* points = (const float*)d_in[1];
    const float* W0  = (const float*)d_in[2];
    const float* b0  = (const float*)d_in[3];
    const float* g0  = (const float*)d_in[4];
    const float* be0 = (const float*)d_in[5];
    const float* W1  = (const float*)d_in[6];
    const float* b1  = (const float*)d_in[7];
    const float* g1  = (const float*)d_in[8];
    const float* be1 = (const float*)d_in[9];
    const float* W2  = (const float*)d_in[10];
    const float* b2  = (const float*)d_in[11];
    const float* g2  = (const float*)d_in[12];
    const float* be2 = (const float*)d_in[13];
    float* out = (float*)d_out;
    (void)in_sizes; (void)n_in; (void)out_size;

    prep_k<<<128, 256>>>(xyz);                         // 1
    pq_k<<<4096, 256>>>(W0, b0, points);               // 2
    knn_k<<<4096, 256>>>();                            // 3
    stats0_k<<<4096, 256>>>();                         // 4
    finalize_k<<<1, 128>>>(g0, be0, 0, 64);            // 5
    layer1_k<<<4096, 256>>>(W1, b1);                   // 6  <- ncu -s 5 -c 1 captures this
    stats1_k<<<dim3(8, 128), 256>>>();                 // 7
    finalize_k<<<1, 128>>>(g1, be1, 64, 64);           // 8
    layer2_k<<<4096, 256>>>(W2, b2);                   // 9
    finalize_k<<<1, 128>>>(g2, be2, 128, 128);         // 10
    out_k<<<16384, 256>>>(out);                        // 11
}

// round 14
// speedup vs baseline: 1.2784x; 1.0676x over previous
#include <cuda_runtime.h>
#include <cstdint>
#include <cstddef>

#define FULLW 0xffffffffu
typedef unsigned long long ull;

// ---------------- static device scratch (allocation is forbidden) ----------------
__device__ float4 g_xyz4[32768];                      // (x,y,z,|p|^2)
__device__ int    g_idx[32768 * 32];                  // 32-NN global point ids
__device__ float  g_P[32768 * 64];                    // per-point partial of z0 (8MB, L2-resident)
__device__ float  g_Q[32768 * 64];                    // per-query partial of z0
__device__ float  g_z1[(size_t)32768 * 64 * 32];      // z1 [q][64][32]
__device__ float2 g_mm[(size_t)32768 * 128];          // per (q,ch): (max_k z2, min_k z2)
__device__ double g_sum[256];                         // BN sums: L0 0..63, L1 64..127, L2 128..255
__device__ double g_sq[256];
__device__ float  g_scale[256];                       // folded BN affine
__device__ float  g_shift[256];

// ---------------- packed f32x2 helpers (exact fp32 semantics) ----------------
__device__ __forceinline__ ull pack2(float lo, float hi)
{
    ull r; asm("mov.b64 %0, {%1,%2};" : "=l"(r) : "f"(lo), "f"(hi)); return r;
}
__device__ __forceinline__ void unpack2(ull v, float& lo, float& hi)
{
    asm("mov.b64 {%0,%1}, %2;" : "=f"(lo), "=f"(hi) : "l"(v));
}
__device__ __forceinline__ ull ffma2(ull a, ull b, ull c)
{
    ull d; asm("fma.rn.f32x2 %0, %1, %2, %3;" : "=l"(d) : "l"(a), "l"(b), "l"(c)); return d;
}
__device__ __forceinline__ ull fmul2(ull a, ull b)
{
    ull d; asm("mul.rn.f32x2 %0, %1, %2;" : "=l"(d) : "l"(a), "l"(b)); return d;
}
__device__ __forceinline__ ull fadd2(ull a, ull b)
{
    ull d; asm("add.rn.f32x2 %0, %1, %2;" : "=l"(d) : "l"(a), "l"(b)); return d;
}

// monotone float<->uint order transform
__device__ __forceinline__ unsigned ford(float f)
{
    unsigned b = __float_as_uint(f);
    return (b & 0x80000000u) ? ~b : (b | 0x80000000u);
}
__device__ __forceinline__ float iford(unsigned u)
{
    unsigned b = (u & 0x80000000u) ? (u & 0x7fffffffu) : ~u;
    return __uint_as_float(b);
}

// ---------------- prep: pack xyz + squared norm, zero stats ----------------
__global__ void prep_k(const float* __restrict__ xyz)
{
    int i = blockIdx.x * 256 + threadIdx.x;           // 0..32767
    float x = xyz[3 * i + 0], y = xyz[3 * i + 1], z = xyz[3 * i + 2];
    g_xyz4[i] = make_float4(x, y, z, x * x + y * y + z * z);
    if (blockIdx.x == 0) {                            // replay-safe stats reset
        g_sum[threadIdx.x] = 0.0;
        g_sq[threadIdx.x]  = 0.0;
    }
}

// ---------------- P/Q tables: z0[q,k,o] = P[nb][o] + Q[q][o] ----------------
// P[p][o] = W0[o,0:3].xyz[p] + W0[o,3:67].points[p];  Q[q][o] = b0[o] - W0[o,0:3].xyz[q]
__global__ void __launch_bounds__(256) pq_k(const float* __restrict__ W0,
                                            const float* __restrict__ b0,
                                            const float* __restrict__ points)
{
    __shared__ float swt[67 * 64];                    // [c][o]
    int tid = threadIdx.x;
    for (int i = tid; i < 64 * 67; i += 256) {
        int o = i / 67, c = i - o * 67;
        swt[c * 64 + o] = W0[i];
    }
    __syncthreads();

    int lane = tid & 31;
    int p    = blockIdx.x * 8 + (tid >> 5);

    float f[67];
    float4 cp = g_xyz4[p];
    f[0] = cp.x; f[1] = cp.y; f[2] = cp.z;
    const float4* pf = (const float4*)(points + (size_t)p * 64);   // broadcast within warp
#pragma unroll
    for (int i = 0; i < 16; i++) {
        float4 v = pf[i];
        f[3 + 4 * i] = v.x; f[4 + 4 * i] = v.y;
        f[5 + 4 * i] = v.z; f[6 + 4 * i] = v.w;
    }

#pragma unroll
    for (int h = 0; h < 2; h++) {
        int o = h * 32 + lane;
        float acc = 0.0f;
#pragma unroll 16
        for (int c = 0; c < 67; c++)
            acc = fmaf(swt[c * 64 + o], f[c], acc);
        g_P[p * 64 + o] = acc;
        float qv = b0[o] - fmaf(swt[o], f[0],
                         fmaf(swt[64 + o], f[1], swt[128 + o] * f[2]));
        g_Q[p * 64 + o] = qv;
    }
}

// ---------------- kNN: warp per query, evict-max top-32 via REDUX ----------------
__global__ void knn_k()
{
    int lane  = threadIdx.x & 31;
    int q     = blockIdx.x * 8 + (threadIdx.x >> 5);
    int bbase = q & ~4095;

    float4 cq = g_xyz4[q];
    float  qsq = cq.w;

    unsigned key = 0xFFFFFFE0u | (unsigned)lane;
    unsigned thr = 0xFFFFFFFFu;
    int      ki  = bbase;

    for (int base = 0; base < 4096; base += 32) {
        float4 cn  = g_xyz4[bbase + base + lane];
        float  dot = fmaf(cq.x, cn.x, fmaf(cq.y, cn.y, cq.z * cn.z));
        float  d   = fmaf(-2.0f, dot, qsq + cn.w);
        unsigned uc = ford(d);

        unsigned m = __ballot_sync(FULLW, uc < (thr & ~31u));
        while (m) {
            int src = __ffs(m) - 1; m &= m - 1;
            unsigned ucs = __shfl_sync(FULLW, uc, src);
            if (ucs < (thr & ~31u)) {
                if (lane == (int)(thr & 31u)) {
                    key = (ucs & ~31u) | (unsigned)lane;
                    ki  = bbase + base + src;
                }
                thr = __reduce_max_sync(FULLW, key);
            }
        }
    }
    g_idx[q * 32 + lane] = ki;
}

// ---------------- stats of z0: lane = channel pair, COALESCED loop over neighbors ----------------
// No shuffles: after the loop each lane already holds the per-channel partials.
__global__ void __launch_bounds__(256) stats0_k()
{
    __shared__ float ss[64], ss2[64];
    int tid = threadIdx.x;
    if (tid < 64) { ss[tid] = 0.0f; ss2[tid] = 0.0f; }
    __syncthreads();

    int lane = tid & 31;
    int q    = blockIdx.x * 8 + (tid >> 5);
    int nb_l = g_idx[q * 32 + lane];                   // coalesced; broadcast via shfl below

    float2 qv = *(const float2*)(g_Q + (size_t)q * 64 + 2 * lane);   // coalesced 256B
    ull q2 = pack2(qv.x, qv.y);

    ull s = 0ull, s2 = 0ull;                           // bits of (0.0f, 0.0f)
#pragma unroll 4
    for (int j = 0; j < 32; j++) {
        int nbj = __shfl_sync(FULLW, nb_l, j);
        float2 pv = *(const float2*)(g_P + (size_t)nbj * 64 + 2 * lane);  // coalesced 256B
        ull z = fadd2(pack2(pv.x, pv.y), q2);
        s  = fadd2(s, z);
        s2 = ffma2(z, z, s2);
    }
    float slo, shi, tlo, thi;
    unpack2(s, slo, shi); unpack2(s2, tlo, thi);
    atomicAdd(&ss[2 * lane], slo);      atomicAdd(&ss[2 * lane + 1], shi);
    atomicAdd(&ss2[2 * lane], tlo);     atomicAdd(&ss2[2 * lane + 1], thi);
    __syncthreads();
    if (tid < 64) {
        atomicAdd(&g_sum[tid], (double)ss[tid]);
        atomicAdd(&g_sq[tid],  (double)ss2[tid]);
    }
}

// ---------------- layer 1: smem-staged gather, BN+ReLU, GEMM 64x64 (f32x2) ----------------
// Per warp: 4 phases of 16 channels; each phase stages P rows for all 32 neighbors
// cooperatively (64B segments), then the GEMM accumulates into 32 persistent f32x2 accs.
__global__ void __launch_bounds__(256) layer1_k(const float* __restrict__ W1,
                                                const float* __restrict__ b1)
{
    __shared__ float swt[64 * 64];                    // [c][o]
    __shared__ float sb[64];
    __shared__ float stg[8][33][17];                  // [warp][nb(32)+Qrow(1)][16+pad]
    int tid = threadIdx.x;
    for (int i = tid; i < 64 * 64; i += 256) {
        int o = i >> 6, c = i & 63;
        swt[c * 64 + o] = W1[i];
    }
    if (tid < 64) sb[tid] = b1[tid];
    __syncthreads();

    int lane = tid & 31;
    int w    = tid >> 5;
    int q    = blockIdx.x * 8 + w;
    int nb_l = g_idx[q * 32 + lane];

    ull acc[32];
#pragma unroll
    for (int p = 0; p < 32; p++)
        acc[p] = pack2(sb[2 * p], sb[2 * p + 1]);

    int grp = lane >> 3;                              // 0..3: which nb in each load round
    int off = (lane & 7) * 2;                         // 0..14: float2 offset in chunk

#pragma unroll 1
    for (int t = 0; t < 4; t++) {                     // 16-channel phases
        // stage P[nb_j][16t..16t+15] for j=0..31 (8 rounds x 4 rows, 64B segments)
#pragma unroll
        for (int g = 0; g < 8; g++) {
            int j   = g * 4 + grp;
            int nbj = __shfl_sync(FULLW, nb_l, j);
            float2 v = *(const float2*)(g_P + (size_t)nbj * 64 + t * 16 + off);
            stg[w][j][off] = v.x; stg[w][j][off + 1] = v.y;
        }
        if (lane < 8) {                               // stage Q chunk as row 32
            float2 v = *(const float2*)(g_Q + (size_t)q * 64 + t * 16 + off);
            stg[w][32][off] = v.x; stg[w][32][off + 1] = v.y;
        }
        __syncwarp();

#pragma unroll 4
        for (int cl = 0; cl < 16; cl++) {
            int c = t * 16 + cl;
            float z  = stg[w][lane][cl] + stg[w][32][cl];    // conflict-free (stride 17)
            float fv = fmaxf(fmaf(z, g_scale[c], g_shift[c]), 0.0f);
            ull f2 = pack2(fv, fv);
            const ulonglong2* wr = (const ulonglong2*)(swt + c * 64);
#pragma unroll
            for (int p2 = 0; p2 < 16; p2++) {         // broadcast LDS.128 -> 2 ch-pairs
                ulonglong2 wv = wr[p2];
                acc[2 * p2 + 0] = ffma2(wv.x, f2, acc[2 * p2 + 0]);
                acc[2 * p2 + 1] = ffma2(wv.y, f2, acc[2 * p2 + 1]);
            }
        }
        __syncwarp();                                 // protect stg before restage
    }

    float* dst = g_z1 + (size_t)q * 2048 + lane;
#pragma unroll
    for (int p = 0; p < 32; p++) {
        float lo, hi; unpack2(acc[p], lo, hi);
        dst[(size_t)(2 * p + 0) * 32] = lo;           // coalesced per channel
        dst[(size_t)(2 * p + 1) * 32] = hi;
    }
}

// ---------------- BN stats over z1 (coalesced column-strided) ----------------
__global__ void stats1_k()
{
    int col   = blockIdx.x * 256 + threadIdx.x;        // 0..2047
    int qbase = blockIdx.y * 256;
    const float* p = g_z1 + (size_t)qbase * 2048 + col;
    float s = 0.0f, s2 = 0.0f;
#pragma unroll 8
    for (int i = 0; i < 256; i++) {
        float v = p[(size_t)i * 2048];
        s += v;
        s2 = fmaf(v, v, s2);
    }
#pragma unroll
    for (int off = 16; off; off >>= 1) {               // warp spans exactly one channel
        s  += __shfl_xor_sync(FULLW, s,  off);
        s2 += __shfl_xor_sync(FULLW, s2, off);
    }
    if ((threadIdx.x & 31) == 0) {
        int ch = 64 + (col >> 5);
        atomicAdd(&g_sum[ch], (double)s);
        atomicAdd(&g_sq[ch],  (double)s2);
    }
}

// ---------------- layer 2: GEMM 64x128 + fused per-(q,ch) max/min + BN stats ----------------
// z2 is never written to HBM.
__global__ void __launch_bounds__(256) layer2_k(const float* __restrict__ W2,
                                                const float* __restrict__ b2)
{
    __shared__ float swt[64 * 128];                   // [c][o]
    __shared__ float sb[128];
    __shared__ float ss[128], ss2[128];
    int tid = threadIdx.x;
    for (int i = tid; i < 128 * 64; i += 256) {
        int o = i >> 6, c = i & 63;
        swt[c * 128 + o] = W2[i];
    }
    if (tid < 128) { sb[tid] = b2[tid]; ss[tid] = 0.0f; ss2[tid] = 0.0f; }
    __syncthreads();

    int lane = tid & 31;
    int q    = blockIdx.x * 8 + (tid >> 5);
    const float* src = g_z1 + (size_t)q * 2048 + lane;

    float f[64];
#pragma unroll
    for (int c = 0; c < 64; c++) {
        float z = src[(size_t)c * 32];                // coalesced
        f[c] = fmaxf(fmaf(z, g_scale[64 + c], g_shift[64 + c]), 0.0f);
    }

#pragma unroll
    for (int h = 0; h < 4; h++) {                     // 4 chunks of 32 outputs
        ull acc[16];
#pragma unroll
        for (int p = 0; p < 16; p++)
            acc[p] = pack2(sb[h * 32 + 2 * p], sb[h * 32 + 2 * p + 1]);
#pragma unroll 16
        for (int c = 0; c < 64; c++) {
            ull f2 = pack2(f[c], f[c]);
            const ulonglong2* wr = (const ulonglong2*)(swt + c * 128 + h * 32);
#pragma unroll
            for (int p2 = 0; p2 < 8; p2++) {          // full 32-channel chunk
                ulonglong2 w = wr[p2];
                acc[2 * p2 + 0] = ffma2(w.x, f2, acc[2 * p2 + 0]);
                acc[2 * p2 + 1] = ffma2(w.y, f2, acc[2 * p2 + 1]);
            }
        }

        // fused epilogue: REDUX max/min per channel + butterfly sums (no z2 store)
        ull my_s = 0, my_s2 = 0;
        float2 m0 = make_float2(0, 0), m1 = make_float2(0, 0);
#pragma unroll
        for (int p = 0; p < 16; p++) {
            float lo, hi; unpack2(acc[p], lo, hi);
            unsigned mxlo = __reduce_max_sync(FULLW, ford(lo));
            unsigned mnlo = __reduce_min_sync(FULLW, ford(lo));
            unsigned mxhi = __reduce_max_sync(FULLW, ford(hi));
            unsigned mnhi = __reduce_min_sync(FULLW, ford(hi));
            ull s = acc[p], s2 = fmul2(acc[p], acc[p]);
#pragma unroll
            for (int off = 16; off; off >>= 1) {
                s  = fadd2(s,  __shfl_xor_sync(FULLW, s,  off));
                s2 = fadd2(s2, __shfl_xor_sync(FULLW, s2, off));
            }
            if (lane == p) {
                my_s = s; my_s2 = s2;
                m0 = make_float2(iford(mxlo), iford(mnlo));
                m1 = make_float2(iford(mxhi), iford(mnhi));
            }
        }
        if (lane < 16) {
            int ch = h * 32 + 2 * lane;
            g_mm[(size_t)q * 128 + ch]     = m0;
            g_mm[(size_t)q * 128 + ch + 1] = m1;
            float slo, shi, tlo, thi;
            unpack2(my_s, slo, shi); unpack2(my_s2, tlo, thi);
            atomicAdd(&ss[ch], slo);      atomicAdd(&ss[ch + 1], shi);
            atomicAdd(&ss2[ch], tlo);     atomicAdd(&ss2[ch + 1], thi);
        }
    }
    __syncthreads();
    if (tid < 128) {
        atomicAdd(&g_sum[128 + tid], (double)ss[tid]);
        atomicAdd(&g_sq[128 + tid],  (double)ss2[tid]);
    }
}

// ---------------- fold BN (batch stats) into scale/shift ----------------
__global__ void finalize_k(const float* __restrict__ g, const float* __restrict__ beta,
                           int chan_base, int n)
{
    int o = threadIdx.x;
    if (o >= n) return;
    const double cnt = 1048576.0;                      // 8*4096*32
    double mean = g_sum[chan_base + o] / cnt;
    double var  = g_sq[chan_base + o] / cnt - mean * mean;   // biased, matches ref
    if (var < 0.0) var = 0.0;
    double sc = (double)g[o] / sqrt(var + 1e-5);
    g_scale[chan_base + o] = (float)sc;
    g_shift[chan_base + o] = (float)((double)beta[o] - mean * sc);
}

// ---------------- tiny epilogue: monotone BN+ReLU through stored max/min ----------------
__global__ void out_k(float* __restrict__ out)
{
    int idx = blockIdx.x * 256 + threadIdx.x;          // q*128 + o
    int o = idx & 127;
    float2 mm = g_mm[idx];
    float a = g_scale[128 + o], c = g_shift[128 + o];
    float m = (a >= 0.0f) ? mm.x : mm.y;               // max_k relu(a z + c)
    out[idx] = fmaxf(fmaf(a, m, c), 0.0f);
}

// ---------------- launch: linear chain, graph-capturable ----------------
extern "C" void kernel_launch(void* const* d_in, const int* in_sizes, int n_in,
                              void* d_out, int out_size)
{
    const float* xyz    = (const float*)d_in[0];
    const float* points = (const float*)d_in[1];
    const float* W0  = (const float*)d_in[2];
    const float* b0  = (const float*)d_in[3];
    const float* g0  = (const float*)d_in[4];
    const float* be0 = (const float*)d_in[5];
    const float* W1  = (const float*)d_in[6];
    const float* b1  = (const float*)d_in[7];
    const float* g1  = (const float*)d_in[8];
    const float* be1 = (const float*)d_in[9];
    const float* W2  = (const float*)d_in[10];
    const float* b2  = (const float*)d_in[11];
    const float* g2  = (const float*)d_in[12];
    const float* be2 = (const float*)d_in[13];
    float* out = (float*)d_out;
    (void)in_sizes; (void)n_in; (void)out_size;

    prep_k<<<128, 256>>>(xyz);                         // 1
    pq_k<<<4096, 256>>>(W0, b0, points);               // 2
    knn_k<<<4096, 256>>>();                            // 3
    stats0_k<<<4096, 256>>>();                         // 4
    finalize_k<<<1, 128>>>(g0, be0, 0, 64);            // 5
    layer1_k<<<4096, 256>>>(W1, b1);                   // 6
    stats1_k<<<dim3(8, 128), 256>>>();                 // 7
    finalize_k<<<1, 128>>>(g1, be1, 64, 64);           // 8
    layer2_k<<<4096, 256>>>(W2, b2);                   // 9
    finalize_k<<<1, 128>>>(g2, be2, 128, 128);         // 10
    out_k<<<16384, 256>>>(out);                        // 11
}